// round 2
// baseline (speedup 1.0000x reference)
#include <cuda_runtime.h>
#include <math.h>

#define NN 100000
#define NE 1600000
#define EP (NE + NN)          // edges + self loops
#define HID 64
#define LAYERS 3

// ---------------- scratch (device globals; no allocation allowed) ----------
__device__ float g_x[NN * HID];      // current features / residual
__device__ float g_xl[NN * HID];
__device__ float g_xr[NN * HID];
__device__ float g_out[NN * HID];    // aggregation target
__device__ float g_score[EP * 2];    // per-edge exp(score) per head
__device__ float g_denom[NN * 2];    // softmax denominators

// ---------------- 1) input projection: x = coords @ Wp + bp ----------------
__global__ void k_proj(const float* __restrict__ coords,
                       const float* __restrict__ Wp,
                       const float* __restrict__ bp) {
    int i = blockIdx.x * blockDim.x + threadIdx.x;
    if (i >= NN * HID) return;
    int n = i >> 6, c = i & 63;
    float c0 = coords[n * 2 + 0];
    float c1 = coords[n * 2 + 1];
    g_x[i] = fmaf(c0, Wp[c], fmaf(c1, Wp[64 + c], bp[c]));
}

// ---------------- 2) fused GEMM: xl = x@Wl+bl ; xr = x@Wr+br ----------------
// 32 rows per block, 256 threads: tx in [0,32) owns 4 cols (of 128 combined),
// ty in [0,8) owns 4 rows.
__global__ __launch_bounds__(256, 4)
void k_gemm(const float* __restrict__ Wl, const float* __restrict__ bl,
            const float* __restrict__ Wr, const float* __restrict__ br) {
    __shared__ float Ws[64][128];    // combined [k][c]: c<64 -> Wl, c>=64 -> Wr
    __shared__ float xs[32][64];
    int tid  = threadIdx.x;
    int row0 = blockIdx.x * 32;

    for (int j = tid; j < 64 * 128; j += 256) {
        int k = j >> 7, c = j & 127;
        Ws[k][c] = (c < 64) ? Wl[k * 64 + c] : Wr[k * 64 + (c - 64)];
    }
    for (int j = tid; j < 32 * 16; j += 256) {
        int r = j >> 4, kq = j & 15;
        *(float4*)&xs[r][kq * 4] =
            *(const float4*)&g_x[(row0 + r) * 64 + kq * 4];
    }
    __syncthreads();

    int tx = tid & 31, ty = tid >> 5;
    float4 acc[4];
#pragma unroll
    for (int r = 0; r < 4; r++) acc[r] = make_float4(0.f, 0.f, 0.f, 0.f);

#pragma unroll 16
    for (int k = 0; k < 64; k++) {
        float4 w = *(float4*)&Ws[k][tx * 4];
#pragma unroll
        for (int r = 0; r < 4; r++) {
            float xv = xs[ty * 4 + r][k];
            acc[r].x = fmaf(xv, w.x, acc[r].x);
            acc[r].y = fmaf(xv, w.y, acc[r].y);
            acc[r].z = fmaf(xv, w.z, acc[r].z);
            acc[r].w = fmaf(xv, w.w, acc[r].w);
        }
    }

    int c0 = tx * 4;
    float4 bias;
    float* dst;
    if (c0 < 64) { bias = *(const float4*)&bl[c0];       dst = g_xl; }
    else         { bias = *(const float4*)&br[c0 - 64];  dst = g_xr; c0 -= 64; }
#pragma unroll
    for (int r = 0; r < 4; r++) {
        float4 v = acc[r];
        v.x += bias.x; v.y += bias.y; v.z += bias.z; v.w += bias.w;
        *(float4*)&dst[(row0 + ty * 4 + r) * 64 + c0] = v;
    }
}

// ---------------- 3) init: out = bias_out (broadcast), denom = 0 -----------
__global__ void k_init(const float* __restrict__ bias_out) {
    int i = blockIdx.x * blockDim.x + threadIdx.x;
    if (i >= NN * HID) return;
    g_out[i] = bias_out[i & 63];
    if (i < NN * 2) g_denom[i] = 0.f;
}

// ---------------- 4) edge pass A: scores + exp + denom ---------------------
// 16 threads per edge; lane covers dims lane*4..lane*4+3; head = lane>>3.
__global__ __launch_bounds__(256)
void k_score(const int* __restrict__ ei, const float* __restrict__ att) {
    int t = blockIdx.x * 256 + threadIdx.x;
    int e = t >> 4;
    if (e >= EP) return;
    int lane = t & 15;

    int s, d;
    if (e < NE) { s = ei[e]; d = ei[NE + e]; }
    else        { s = e - NE; d = s; }

    float4 a = *(const float4*)&g_xl[s * 64 + lane * 4];
    float4 b = *(const float4*)&g_xr[d * 64 + lane * 4];
    float4 v;
    v.x = a.x + b.x; v.y = a.y + b.y; v.z = a.z + b.z; v.w = a.w + b.w;
    v.x = v.x > 0.f ? v.x : 0.2f * v.x;
    v.y = v.y > 0.f ? v.y : 0.2f * v.y;
    v.z = v.z > 0.f ? v.z : 0.2f * v.z;
    v.w = v.w > 0.f ? v.w : 0.2f * v.w;
    float4 at = *(const float4*)&att[lane * 4];  // flat [h*32+dim] == lane*4
    float p = v.x * at.x + v.y * at.y + v.z * at.z + v.w * at.w;
    p += __shfl_down_sync(0xffffffffu, p, 4, 8);
    p += __shfl_down_sync(0xffffffffu, p, 2, 8);
    p += __shfl_down_sync(0xffffffffu, p, 1, 8);
    if ((lane & 7) == 0) {
        float ex = __expf(p);               // scores are O(1): no max needed
        int h = lane >> 3;
        g_score[e * 2 + h] = ex;
        atomicAdd(&g_denom[d * 2 + h], ex);
    }
}

// ---------------- 5) edge pass B: alpha * xl[src] -> out[dst] --------------
__global__ __launch_bounds__(256)
void k_aggr(const int* __restrict__ ei) {
    int t = blockIdx.x * 256 + threadIdx.x;
    int e = t >> 4;
    if (e >= EP) return;
    int lane = t & 15;

    int s, d;
    if (e < NE) { s = ei[e]; d = ei[NE + e]; }
    else        { s = e - NE; d = s; }

    int h = lane >> 3;
    float ex = g_score[e * 2 + h];
    float dn = g_denom[d * 2 + h];
    float alpha = ex / (dn + 1e-16f);

    float4 a = *(const float4*)&g_xl[s * 64 + lane * 4];
    float mx = alpha * a.x, my = alpha * a.y, mz = alpha * a.z, mw = alpha * a.w;
    float* p = &g_out[d * 64 + lane * 4];
    asm volatile("red.global.add.v4.f32 [%0], {%1,%2,%3,%4};"
                 :: "l"(p), "f"(mx), "f"(my), "f"(mz), "f"(mw) : "memory");
}

// ---------------- 6) post: ELU + residual + LayerNorm + nan_to_num ---------
__device__ __forceinline__ float nan2num(float o) {
    if (!isfinite(o)) o = isnan(o) ? 0.f : (o > 0.f ? 1e6f : -1e6f);
    return o;
}

__global__ __launch_bounds__(256)
void k_post(const float* __restrict__ gamma, const float* __restrict__ beta,
            float* __restrict__ dout, int to_dout) {
    int w = (blockIdx.x * blockDim.x + threadIdx.x) >> 5;
    if (w >= NN) return;
    int l = threadIdx.x & 31;
    int base = w * 64;

    float v0 = g_out[base + l];
    float v1 = g_out[base + 32 + l];
    v0 = v0 > 0.f ? v0 : expm1f(v0);     // ELU
    v1 = v1 > 0.f ? v1 : expm1f(v1);
    float y0 = v0 + g_x[base + l];       // residual
    float y1 = v1 + g_x[base + 32 + l];

    float sum = y0 + y1;
#pragma unroll
    for (int o = 16; o; o >>= 1) sum += __shfl_xor_sync(0xffffffffu, sum, o);
    float mu = sum * (1.f / 64.f);
    float d0 = y0 - mu, d1 = y1 - mu;
    float vs = d0 * d0 + d1 * d1;
#pragma unroll
    for (int o = 16; o; o >>= 1) vs += __shfl_xor_sync(0xffffffffu, vs, o);
    float r = rsqrtf(vs * (1.f / 64.f) + 1e-5f);

    float o0 = nan2num(fmaf(d0 * r, gamma[l],      beta[l]));
    float o1 = nan2num(fmaf(d1 * r, gamma[32 + l], beta[32 + l]));

    float* outp = to_dout ? dout : g_x;
    outp[base + l]      = o0;
    outp[base + 32 + l] = o1;
}

// ---------------- host driver ----------------------------------------------
extern "C" void kernel_launch(void* const* d_in, const int* in_sizes, int n_in,
                              void* d_out, int out_size) {
    const float* coords   = (const float*)d_in[0];
    const int*   ei       = (const int*)  d_in[1];   // int32 (JAX x64 disabled)
    const float* Wp       = (const float*)d_in[2];
    const float* bp       = (const float*)d_in[3];
    const float* Wl       = (const float*)d_in[4];
    const float* bl       = (const float*)d_in[5];
    const float* Wr       = (const float*)d_in[6];
    const float* br       = (const float*)d_in[7];
    const float* att      = (const float*)d_in[8];
    const float* bias_out = (const float*)d_in[9];
    const float* gamma    = (const float*)d_in[10];
    const float* beta     = (const float*)d_in[11];
    float*       outp     = (float*)d_out;

    const int TB = 256;
    const int grid_nh  = (NN * HID + TB - 1) / TB;   // 25000
    const int grid_gm  = NN / 32;                    // 3125
    const int grid_eg  = (EP * 16 + TB - 1) / TB;    // 106250
    const int grid_pn  = (NN * 32 + TB - 1) / TB;    // 12500 (warp/node)

    k_proj<<<grid_nh, TB>>>(coords, Wp, bp);

    for (int i = 0; i < LAYERS; i++) {
        k_gemm<<<grid_gm, TB>>>(Wl + i * HID * HID, bl + i * HID,
                                Wr + i * HID * HID, br + i * HID);
        k_init<<<grid_nh, TB>>>(bias_out + i * HID);
        k_score<<<grid_eg, TB>>>(ei, att + i * HID);
        k_aggr<<<grid_eg, TB>>>(ei);
        k_post<<<grid_pn, TB>>>(gamma + i * HID, beta + i * HID,
                                outp, (i == LAYERS - 1) ? 1 : 0);
    }
}

// round 3
// speedup vs baseline: 1.5274x; 1.5274x over previous
#include <cuda_runtime.h>
#include <math.h>

#define NN 100000
#define NE 1600000
#define EP (NE + NN)          // edges + self loops
#define HID 64
#define LAYERS 3

// ---------------- scratch (device globals; no allocation allowed) ----------
__device__ float g_x[NN * HID];      // current features / residual
__device__ float g_xl[NN * HID];
__device__ float g_xr[NN * HID];
__device__ float g_out[NN * HID];    // unnormalized aggregation target
__device__ float g_denom[NN * 2];    // softmax denominators

// ---------------- 1) input projection: x = coords @ Wp + bp ----------------
__global__ void k_proj(const float* __restrict__ coords,
                       const float* __restrict__ Wp,
                       const float* __restrict__ bp) {
    int i = blockIdx.x * blockDim.x + threadIdx.x;
    if (i >= NN * HID) return;
    int n = i >> 6, c = i & 63;
    float c0 = coords[n * 2 + 0];
    float c1 = coords[n * 2 + 1];
    g_x[i] = fmaf(c0, Wp[c], fmaf(c1, Wp[64 + c], bp[c]));
}

// ---------------- 2) fused GEMM: xl = x@Wl+bl ; xr = x@Wr+br ----------------
__global__ __launch_bounds__(256, 4)
void k_gemm(const float* __restrict__ Wl, const float* __restrict__ bl,
            const float* __restrict__ Wr, const float* __restrict__ br) {
    __shared__ float Ws[64][128];    // combined [k][c]: c<64 -> Wl, c>=64 -> Wr
    __shared__ float xs[32][64];
    int tid  = threadIdx.x;
    int row0 = blockIdx.x * 32;

    for (int j = tid; j < 64 * 128; j += 256) {
        int k = j >> 7, c = j & 127;
        Ws[k][c] = (c < 64) ? Wl[k * 64 + c] : Wr[k * 64 + (c - 64)];
    }
    for (int j = tid; j < 32 * 16; j += 256) {
        int r = j >> 4, kq = j & 15;
        *(float4*)&xs[r][kq * 4] =
            *(const float4*)&g_x[(row0 + r) * 64 + kq * 4];
    }
    __syncthreads();

    int tx = tid & 31, ty = tid >> 5;
    float4 acc[4];
#pragma unroll
    for (int r = 0; r < 4; r++) acc[r] = make_float4(0.f, 0.f, 0.f, 0.f);

#pragma unroll 16
    for (int k = 0; k < 64; k++) {
        float4 w = *(float4*)&Ws[k][tx * 4];
#pragma unroll
        for (int r = 0; r < 4; r++) {
            float xv = xs[ty * 4 + r][k];
            acc[r].x = fmaf(xv, w.x, acc[r].x);
            acc[r].y = fmaf(xv, w.y, acc[r].y);
            acc[r].z = fmaf(xv, w.z, acc[r].z);
            acc[r].w = fmaf(xv, w.w, acc[r].w);
        }
    }

    int c0 = tx * 4;
    float4 bias;
    float* dst;
    if (c0 < 64) { bias = *(const float4*)&bl[c0];       dst = g_xl; }
    else         { bias = *(const float4*)&br[c0 - 64];  dst = g_xr; c0 -= 64; }
#pragma unroll
    for (int r = 0; r < 4; r++) {
        float4 v = acc[r];
        v.x += bias.x; v.y += bias.y; v.z += bias.z; v.w += bias.w;
        *(float4*)&dst[(row0 + ty * 4 + r) * 64 + c0] = v;
    }
}

// ---------------- 3) init: out = 0, denom = 0 -------------------------------
__global__ void k_init() {
    int i = blockIdx.x * blockDim.x + threadIdx.x;
    if (i >= NN * HID) return;
    g_out[i] = 0.f;
    if (i < NN * 2) g_denom[i] = 0.f;
}

// ---------------- 4) FUSED edge pass: score + exp + weighted scatter -------
// 16 threads/edge; lane covers dims lane*4..lane*4+3; head = lane>>3.
// out[d] += exp(score)*xl[s]  (unnormalized);  denom[d] += exp(score).
__global__ __launch_bounds__(256)
void k_edge(const int* __restrict__ ei, const float* __restrict__ att) {
    int t = blockIdx.x * 256 + threadIdx.x;
    int e = t >> 4;
    if (e >= EP) return;
    int lane = t & 15;

    int s, d;
    if (e < NE) { s = ei[e]; d = ei[NE + e]; }
    else        { s = e - NE; d = s; }

    float4 a = *(const float4*)&g_xl[s * 64 + lane * 4];
    float4 b = *(const float4*)&g_xr[d * 64 + lane * 4];
    float4 v;
    v.x = a.x + b.x; v.y = a.y + b.y; v.z = a.z + b.z; v.w = a.w + b.w;
    v.x = v.x > 0.f ? v.x : 0.2f * v.x;
    v.y = v.y > 0.f ? v.y : 0.2f * v.y;
    v.z = v.z > 0.f ? v.z : 0.2f * v.z;
    v.w = v.w > 0.f ? v.w : 0.2f * v.w;
    float4 at = *(const float4*)&att[lane * 4];  // flat [h*32+dim] == lane*4
    float p = v.x * at.x + v.y * at.y + v.z * at.z + v.w * at.w;
    // butterfly sum within each 8-lane (per-head) group: all lanes get p
    p += __shfl_xor_sync(0xffffffffu, p, 1, 8);
    p += __shfl_xor_sync(0xffffffffu, p, 2, 8);
    p += __shfl_xor_sync(0xffffffffu, p, 4, 8);
    float ex = __expf(p);                 // scores are O(1): no max needed

    float* q = &g_out[d * 64 + lane * 4];
    asm volatile("red.global.add.v4.f32 [%0], {%1,%2,%3,%4};"
                 :: "l"(q), "f"(ex * a.x), "f"(ex * a.y),
                    "f"(ex * a.z), "f"(ex * a.w) : "memory");
    if ((lane & 7) == 0)
        atomicAdd(&g_denom[d * 2 + (lane >> 3)], ex);
}

// ---------------- 5) post: normalize+bias + ELU + residual + LN ------------
__device__ __forceinline__ float nan2num(float o) {
    if (!isfinite(o)) o = isnan(o) ? 0.f : (o > 0.f ? 1e6f : -1e6f);
    return o;
}

__global__ __launch_bounds__(256)
void k_post(const float* __restrict__ bias_out,
            const float* __restrict__ gamma, const float* __restrict__ beta,
            float* __restrict__ dout, int to_dout) {
    int w = (blockIdx.x * blockDim.x + threadIdx.x) >> 5;
    if (w >= NN) return;
    int l = threadIdx.x & 31;
    int base = w * 64;

    float inv0 = 1.f / (g_denom[w * 2 + 0] + 1e-16f);   // head 0 (dims 0..31)
    float inv1 = 1.f / (g_denom[w * 2 + 1] + 1e-16f);   // head 1 (dims 32..63)

    float v0 = g_out[base + l]      * inv0 + bias_out[l];
    float v1 = g_out[base + 32 + l] * inv1 + bias_out[32 + l];
    v0 = v0 > 0.f ? v0 : expm1f(v0);     // ELU
    v1 = v1 > 0.f ? v1 : expm1f(v1);
    float y0 = v0 + g_x[base + l];       // residual
    float y1 = v1 + g_x[base + 32 + l];

    float sum = y0 + y1;
#pragma unroll
    for (int o = 16; o; o >>= 1) sum += __shfl_xor_sync(0xffffffffu, sum, o);
    float mu = sum * (1.f / 64.f);
    float d0 = y0 - mu, d1 = y1 - mu;
    float vs = d0 * d0 + d1 * d1;
#pragma unroll
    for (int o = 16; o; o >>= 1) vs += __shfl_xor_sync(0xffffffffu, vs, o);
    float r = rsqrtf(vs * (1.f / 64.f) + 1e-5f);

    float o0 = nan2num(fmaf(d0 * r, gamma[l],      beta[l]));
    float o1 = nan2num(fmaf(d1 * r, gamma[32 + l], beta[32 + l]));

    float* outp = to_dout ? dout : g_x;
    outp[base + l]      = o0;
    outp[base + 32 + l] = o1;
}

// ---------------- host driver ----------------------------------------------
extern "C" void kernel_launch(void* const* d_in, const int* in_sizes, int n_in,
                              void* d_out, int out_size) {
    const float* coords   = (const float*)d_in[0];
    const int*   ei       = (const int*)  d_in[1];   // int32 (JAX x64 disabled)
    const float* Wp       = (const float*)d_in[2];
    const float* bp       = (const float*)d_in[3];
    const float* Wl       = (const float*)d_in[4];
    const float* bl       = (const float*)d_in[5];
    const float* Wr       = (const float*)d_in[6];
    const float* br       = (const float*)d_in[7];
    const float* att      = (const float*)d_in[8];
    const float* bias_out = (const float*)d_in[9];
    const float* gamma    = (const float*)d_in[10];
    const float* beta     = (const float*)d_in[11];
    float*       outp     = (float*)d_out;

    const int TB = 256;
    const int grid_nh  = (NN * HID + TB - 1) / TB;   // 25000
    const int grid_gm  = NN / 32;                    // 3125
    const int grid_eg  = (EP * 16 + TB - 1) / TB;    // 106250
    const int grid_pn  = (NN * 32 + TB - 1) / TB;    // 12500 (warp/node)

    k_proj<<<grid_nh, TB>>>(coords, Wp, bp);

    for (int i = 0; i < LAYERS; i++) {
        k_gemm<<<grid_gm, TB>>>(Wl + i * HID * HID, bl + i * HID,
                                Wr + i * HID * HID, br + i * HID);
        k_init<<<grid_nh, TB>>>();
        k_edge<<<grid_eg, TB>>>(ei, att + i * HID);
        k_post<<<grid_pn, TB>>>(bias_out + i * HID,
                                gamma + i * HID, beta + i * HID,
                                outp, (i == LAYERS - 1) ? 1 : 0);
    }
}

// round 4
// speedup vs baseline: 2.0384x; 1.3345x over previous
#include <cuda_runtime.h>
#include <math.h>

#define NN 100000
#define NE 1600000
#define EP (NE + NN)          // edges + self loops
#define HID 64
#define LAYERS 3

#define SCAN_T 512
#define NB1 ((NN + SCAN_T - 1) / SCAN_T)   // 196

// ---------------- scratch (device globals; no allocation allowed) ----------
__device__ float g_x[NN * HID];      // current features / residual
__device__ float g_xl[NN * HID];
__device__ float g_xr[NN * HID];
__device__ int   g_deg[NN];          // histogram, then scatter cursor
__device__ int   g_off[NN + 1];      // CSR offsets (exclusive scan)
__device__ int   g_srcs[EP];         // CSR: src node per incoming edge
__device__ int   g_bsum[NB1];        // scan block sums

// ---------------- 1) input projection + zero the degree histogram ----------
__global__ void k_proj(const float* __restrict__ coords,
                       const float* __restrict__ Wp,
                       const float* __restrict__ bp) {
    int i = blockIdx.x * blockDim.x + threadIdx.x;
    if (i >= NN * HID) return;
    int n = i >> 6, c = i & 63;
    float c0 = coords[n * 2 + 0];
    float c1 = coords[n * 2 + 1];
    g_x[i] = fmaf(c0, Wp[c], fmaf(c1, Wp[64 + c], bp[c]));
    if (i < NN) g_deg[i] = 0;
}

// ---------------- 2) CSR build: histogram over destinations ----------------
__global__ void k_hist(const int* __restrict__ ei) {
    int e = blockIdx.x * blockDim.x + threadIdx.x;
    if (e >= EP) return;
    int d = (e < NE) ? ei[NE + e] : (e - NE);
    atomicAdd(&g_deg[d], 1);
}

// ---------------- 3) two-level exclusive scan of g_deg ---------------------
__global__ void k_scan1() {
    __shared__ int s[SCAN_T];
    int t = threadIdx.x, b = blockIdx.x, i = b * SCAN_T + t;
    int v = (i < NN) ? g_deg[i] : 0;
    s[t] = v;
    __syncthreads();
    for (int o = 1; o < SCAN_T; o <<= 1) {
        int u = (t >= o) ? s[t - o] : 0;
        __syncthreads();
        s[t] += u;
        __syncthreads();
    }
    if (i < NN) g_off[i] = s[t] - v;          // exclusive within block
    if (t == SCAN_T - 1) g_bsum[b] = s[t];    // block total
}

__global__ void k_scan2() {
    __shared__ int s[256];
    int t = threadIdx.x;
    int v = (t < NB1) ? g_bsum[t] : 0;
    s[t] = v;
    __syncthreads();
    for (int o = 1; o < 256; o <<= 1) {
        int u = (t >= o) ? s[t - o] : 0;
        __syncthreads();
        s[t] += u;
        __syncthreads();
    }
    if (t < NB1) g_bsum[t] = s[t] - v;        // exclusive block offsets
}

__global__ void k_scan3() {
    int t = threadIdx.x, b = blockIdx.x, i = b * SCAN_T + t;
    if (i < NN) {
        int o = g_off[i] + g_bsum[b];
        g_off[i] = o;
        g_deg[i] = o;                          // reuse as scatter cursor
    }
    if (i == 0) g_off[NN] = EP;
}

// ---------------- 4) CSR scatter --------------------------------------------
__global__ void k_scatter(const int* __restrict__ ei) {
    int e = blockIdx.x * blockDim.x + threadIdx.x;
    if (e >= EP) return;
    int s, d;
    if (e < NE) { s = ei[e]; d = ei[NE + e]; }
    else        { s = e - NE; d = s; }
    int pos = atomicAdd(&g_deg[d], 1);
    g_srcs[pos] = s;
}

// ---------------- 5) fused GEMM: xl = x@Wl+bl ; xr = x@Wr+br ----------------
__global__ __launch_bounds__(256, 4)
void k_gemm(const float* __restrict__ Wl, const float* __restrict__ bl,
            const float* __restrict__ Wr, const float* __restrict__ br) {
    __shared__ float Ws[64][128];    // combined [k][c]: c<64 -> Wl, c>=64 -> Wr
    __shared__ float xs[32][64];
    int tid  = threadIdx.x;
    int row0 = blockIdx.x * 32;

    for (int j = tid; j < 64 * 128; j += 256) {
        int k = j >> 7, c = j & 127;
        Ws[k][c] = (c < 64) ? Wl[k * 64 + c] : Wr[k * 64 + (c - 64)];
    }
    for (int j = tid; j < 32 * 16; j += 256) {
        int r = j >> 4, kq = j & 15;
        *(float4*)&xs[r][kq * 4] =
            *(const float4*)&g_x[(row0 + r) * 64 + kq * 4];
    }
    __syncthreads();

    int tx = tid & 31, ty = tid >> 5;
    float4 acc[4];
#pragma unroll
    for (int r = 0; r < 4; r++) acc[r] = make_float4(0.f, 0.f, 0.f, 0.f);

#pragma unroll 16
    for (int k = 0; k < 64; k++) {
        float4 w = *(float4*)&Ws[k][tx * 4];
#pragma unroll
        for (int r = 0; r < 4; r++) {
            float xv = xs[ty * 4 + r][k];
            acc[r].x = fmaf(xv, w.x, acc[r].x);
            acc[r].y = fmaf(xv, w.y, acc[r].y);
            acc[r].z = fmaf(xv, w.z, acc[r].z);
            acc[r].w = fmaf(xv, w.w, acc[r].w);
        }
    }

    int c0 = tx * 4;
    float4 bias;
    float* dst;
    if (c0 < 64) { bias = *(const float4*)&bl[c0];       dst = g_xl; }
    else         { bias = *(const float4*)&br[c0 - 64];  dst = g_xr; c0 -= 64; }
#pragma unroll
    for (int r = 0; r < 4; r++) {
        float4 v = acc[r];
        v.x += bias.x; v.y += bias.y; v.z += bias.z; v.w += bias.w;
        *(float4*)&dst[(row0 + ty * 4 + r) * 64 + c0] = v;
    }
}

// ---------------- 6) FUSED: per-dst attention + softmax + ELU + LN ---------
// One warp per destination node. Lanes split: half = lane>>4 processes edge
// (beg + 2k + half); l = lane&15 owns dims l*4..l*4+3 (lanes 0-7 head0,
// lanes 8-15 head1). No atomics anywhere.
__device__ __forceinline__ float nan2num(float o) {
    if (!isfinite(o)) o = isnan(o) ? 0.f : (o > 0.f ? 1e6f : -1e6f);
    return o;
}

__global__ __launch_bounds__(256)
void k_aggr_ln(const float* __restrict__ att,
               const float* __restrict__ bias_out,
               const float* __restrict__ gamma, const float* __restrict__ beta,
               float* __restrict__ dout, int to_dout) {
    int w = (blockIdx.x * blockDim.x + threadIdx.x) >> 5;   // node id
    if (w >= NN) return;
    int lane = threadIdx.x & 31;
    int half = lane >> 4;
    int l    = lane & 15;

    int beg = g_off[w], end = g_off[w + 1];

    float4 xr   = *(const float4*)&g_xr[w * 64 + l * 4];
    float4 at4  = *(const float4*)&att[l * 4];   // flat [h*32+dim]

    float4 acc = make_float4(0.f, 0.f, 0.f, 0.f);
    float  dsum = 0.f;

    int iters = (end - beg + 1) >> 1;            // deg >= 1 (self loop)
    for (int k = 0; k < iters; k++) {
        int i = beg + 2 * k + half;
        bool valid = (i < end);
        int  s = valid ? g_srcs[i] : g_srcs[beg];
        float4 a = *(const float4*)&g_xl[s * 64 + l * 4];
        float4 v;
        v.x = a.x + xr.x; v.y = a.y + xr.y;
        v.z = a.z + xr.z; v.w = a.w + xr.w;
        v.x = v.x > 0.f ? v.x : 0.2f * v.x;
        v.y = v.y > 0.f ? v.y : 0.2f * v.y;
        v.z = v.z > 0.f ? v.z : 0.2f * v.z;
        v.w = v.w > 0.f ? v.w : 0.2f * v.w;
        float p = v.x * at4.x + v.y * at4.y + v.z * at4.z + v.w * at4.w;
        // per-head butterfly (width 8): lanes 0-7/16-23 -> head0, 8-15/24-31 -> head1
        p += __shfl_xor_sync(0xffffffffu, p, 1, 8);
        p += __shfl_xor_sync(0xffffffffu, p, 2, 8);
        p += __shfl_xor_sync(0xffffffffu, p, 4, 8);
        float ex = valid ? __expf(p) : 0.f;      // scores O(1): no max shift
        acc.x = fmaf(ex, a.x, acc.x);
        acc.y = fmaf(ex, a.y, acc.y);
        acc.z = fmaf(ex, a.z, acc.z);
        acc.w = fmaf(ex, a.w, acc.w);
        dsum += ex;
    }

    // combine halves (xor 16 is symmetric: both halves end with full sums)
    acc.x += __shfl_xor_sync(0xffffffffu, acc.x, 16);
    acc.y += __shfl_xor_sync(0xffffffffu, acc.y, 16);
    acc.z += __shfl_xor_sync(0xffffffffu, acc.z, 16);
    acc.w += __shfl_xor_sync(0xffffffffu, acc.w, 16);
    dsum  += __shfl_xor_sync(0xffffffffu, dsum, 16);

    // normalize + bias_out + ELU + residual
    float inv = 1.f / (dsum + 1e-16f);           // lane's own head denom
    float4 bo = *(const float4*)&bias_out[l * 4];
    float4 rx = *(const float4*)&g_x[w * 64 + l * 4];
    float y0 = acc.x * inv + bo.x;
    float y1 = acc.y * inv + bo.y;
    float y2 = acc.z * inv + bo.z;
    float y3 = acc.w * inv + bo.w;
    y0 = y0 > 0.f ? y0 : expm1f(y0);
    y1 = y1 > 0.f ? y1 : expm1f(y1);
    y2 = y2 > 0.f ? y2 : expm1f(y2);
    y3 = y3 > 0.f ? y3 : expm1f(y3);
    y0 += rx.x; y1 += rx.y; y2 += rx.z; y3 += rx.w;

    // LayerNorm over 64 dims (butterfly over the 16-lane group)
    float sum = y0 + y1 + y2 + y3;
#pragma unroll
    for (int o = 1; o < 16; o <<= 1)
        sum += __shfl_xor_sync(0xffffffffu, sum, o, 16);
    float mu = sum * (1.f / 64.f);
    float d0 = y0 - mu, d1 = y1 - mu, d2 = y2 - mu, d3 = y3 - mu;
    float vs = d0 * d0 + d1 * d1 + d2 * d2 + d3 * d3;
#pragma unroll
    for (int o = 1; o < 16; o <<= 1)
        vs += __shfl_xor_sync(0xffffffffu, vs, o, 16);
    float r = rsqrtf(vs * (1.f / 64.f) + 1e-5f);

    float4 gm = *(const float4*)&gamma[l * 4];
    float4 bt = *(const float4*)&beta[l * 4];
    float4 o4;
    o4.x = nan2num(fmaf(d0 * r, gm.x, bt.x));
    o4.y = nan2num(fmaf(d1 * r, gm.y, bt.y));
    o4.z = nan2num(fmaf(d2 * r, gm.z, bt.z));
    o4.w = nan2num(fmaf(d3 * r, gm.w, bt.w));

    if (half == 0) {
        float* outp = to_dout ? dout : g_x;
        *(float4*)&outp[w * 64 + l * 4] = o4;
    }
}

// ---------------- host driver ----------------------------------------------
extern "C" void kernel_launch(void* const* d_in, const int* in_sizes, int n_in,
                              void* d_out, int out_size) {
    const float* coords   = (const float*)d_in[0];
    const int*   ei       = (const int*)  d_in[1];   // int32 (JAX x64 disabled)
    const float* Wp       = (const float*)d_in[2];
    const float* bp       = (const float*)d_in[3];
    const float* Wl       = (const float*)d_in[4];
    const float* bl       = (const float*)d_in[5];
    const float* Wr       = (const float*)d_in[6];
    const float* br       = (const float*)d_in[7];
    const float* att      = (const float*)d_in[8];
    const float* bias_out = (const float*)d_in[9];
    const float* gamma    = (const float*)d_in[10];
    const float* beta     = (const float*)d_in[11];
    float*       outp     = (float*)d_out;

    const int TB = 256;
    const int grid_nh = (NN * HID + TB - 1) / TB;    // 25000
    const int grid_gm = NN / 32;                     // 3125
    const int grid_ep = (EP + TB - 1) / TB;          // 6641
    const int grid_ag = (NN * 32 + TB - 1) / TB;     // 12500 (warp/node)

    // projection (+ deg zeroing) and CSR build — once, reused by all layers
    k_proj<<<grid_nh, TB>>>(coords, Wp, bp);
    k_hist<<<grid_ep, TB>>>(ei);
    k_scan1<<<NB1, SCAN_T>>>();
    k_scan2<<<1, 256>>>();
    k_scan3<<<NB1, SCAN_T>>>();
    k_scatter<<<grid_ep, TB>>>(ei);

    for (int i = 0; i < LAYERS; i++) {
        k_gemm<<<grid_gm, TB>>>(Wl + i * HID * HID, bl + i * HID,
                                Wr + i * HID * HID, br + i * HID);
        k_aggr_ln<<<grid_ag, TB>>>(att + i * HID, bias_out + i * HID,
                                   gamma + i * HID, beta + i * HID,
                                   outp, (i == LAYERS - 1) ? 1 : 0);
    }
}

// round 5
// speedup vs baseline: 2.1670x; 1.0631x over previous
#include <cuda_runtime.h>
#include <math.h>

#define NN 100000
#define NE 1600000
#define EP (NE + NN)          // edges + self loops
#define HID 64
#define LAYERS 3

#define SCAN_T 512
#define NB1 ((NN + SCAN_T - 1) / SCAN_T)   // 196

// ---------------- scratch (device globals; no allocation allowed) ----------
__device__ float g_x[NN * HID];      // current features / residual
__device__ float g_xl[NN * HID];
__device__ float g_xr[NN * HID];
__device__ int   g_deg[NN];          // histogram, then scatter cursor
__device__ int   g_off[NN + 1];      // CSR offsets (exclusive scan)
__device__ int   g_srcs[EP];         // CSR: src node per incoming edge
__device__ int   g_bsum[NB1];        // scan block sums

// ---------------- 1) input projection + zero the degree histogram ----------
__global__ void k_proj(const float* __restrict__ coords,
                       const float* __restrict__ Wp,
                       const float* __restrict__ bp) {
    int i = blockIdx.x * blockDim.x + threadIdx.x;
    if (i >= NN * HID) return;
    int n = i >> 6, c = i & 63;
    float c0 = coords[n * 2 + 0];
    float c1 = coords[n * 2 + 1];
    g_x[i] = fmaf(c0, Wp[c], fmaf(c1, Wp[64 + c], bp[c]));
    if (i < NN) g_deg[i] = 0;
}

// ---------------- 2) CSR build: histogram over destinations ----------------
__global__ void k_hist(const int* __restrict__ ei) {
    int e = blockIdx.x * blockDim.x + threadIdx.x;
    if (e >= EP) return;
    int d = (e < NE) ? ei[NE + e] : (e - NE);
    atomicAdd(&g_deg[d], 1);
}

// ---------------- 3) two-level exclusive scan (warp-shuffle based) ---------
__global__ void k_scan1() {
    __shared__ int wsum[SCAN_T / 32];          // 16 warp totals
    int t = threadIdx.x, b = blockIdx.x, i = b * SCAN_T + t;
    int lane = t & 31, wid = t >> 5;
    int v = (i < NN) ? g_deg[i] : 0;
    int x = v;
#pragma unroll
    for (int o = 1; o < 32; o <<= 1) {
        int u = __shfl_up_sync(0xffffffffu, x, o);
        if (lane >= o) x += u;
    }
    if (lane == 31) wsum[wid] = x;
    __syncthreads();
    if (wid == 0) {
        int ws = (lane < SCAN_T / 32) ? wsum[lane] : 0;
        int y = ws;
#pragma unroll
        for (int o = 1; o < 16; o <<= 1) {
            int u = __shfl_up_sync(0xffffffffu, y, o);
            if (lane >= o) y += u;
        }
        if (lane < SCAN_T / 32) wsum[lane] = y - ws;   // exclusive warp offs
        if (lane == SCAN_T / 32 - 1) g_bsum[b] = y;    // block total
    }
    __syncthreads();
    if (i < NN) g_off[i] = x - v + wsum[wid];          // exclusive in block
}

__global__ void k_scan2() {
    __shared__ int wsum[8];
    int t = threadIdx.x, lane = t & 31, wid = t >> 5;
    int v = (t < NB1) ? g_bsum[t] : 0;
    int x = v;
#pragma unroll
    for (int o = 1; o < 32; o <<= 1) {
        int u = __shfl_up_sync(0xffffffffu, x, o);
        if (lane >= o) x += u;
    }
    if (lane == 31) wsum[wid] = x;
    __syncthreads();
    if (wid == 0) {
        int ws = (lane < 8) ? wsum[lane] : 0;
        int y = ws;
#pragma unroll
        for (int o = 1; o < 8; o <<= 1) {
            int u = __shfl_up_sync(0xffffffffu, y, o);
            if (lane >= o) y += u;
        }
        if (lane < 8) wsum[lane] = y - ws;
    }
    __syncthreads();
    if (t < NB1) g_bsum[t] = x - v + wsum[wid];        // exclusive block offs
}

__global__ void k_scan3() {
    int t = threadIdx.x, b = blockIdx.x, i = b * SCAN_T + t;
    if (i < NN) {
        int o = g_off[i] + g_bsum[b];
        g_off[i] = o;
        g_deg[i] = o;                          // reuse as scatter cursor
    }
    if (i == 0) g_off[NN] = EP;
}

// ---------------- 4) CSR scatter --------------------------------------------
__global__ void k_scatter(const int* __restrict__ ei) {
    int e = blockIdx.x * blockDim.x + threadIdx.x;
    if (e >= EP) return;
    int s, d;
    if (e < NE) { s = ei[e]; d = ei[NE + e]; }
    else        { s = e - NE; d = s; }
    int pos = atomicAdd(&g_deg[d], 1);
    g_srcs[pos] = s;
}

// ---------------- 5) fused GEMM: xl = x@Wl+bl ; xr = x@Wr+br ----------------
__global__ __launch_bounds__(256, 4)
void k_gemm(const float* __restrict__ Wl, const float* __restrict__ bl,
            const float* __restrict__ Wr, const float* __restrict__ br) {
    __shared__ float Ws[64][128];    // combined [k][c]: c<64 -> Wl, c>=64 -> Wr
    __shared__ float xs[32][64];
    int tid  = threadIdx.x;
    int row0 = blockIdx.x * 32;

    for (int j = tid; j < 64 * 128; j += 256) {
        int k = j >> 7, c = j & 127;
        Ws[k][c] = (c < 64) ? Wl[k * 64 + c] : Wr[k * 64 + (c - 64)];
    }
    for (int j = tid; j < 32 * 16; j += 256) {
        int r = j >> 4, kq = j & 15;
        *(float4*)&xs[r][kq * 4] =
            *(const float4*)&g_x[(row0 + r) * 64 + kq * 4];
    }
    __syncthreads();

    int tx = tid & 31, ty = tid >> 5;
    float4 acc[4];
#pragma unroll
    for (int r = 0; r < 4; r++) acc[r] = make_float4(0.f, 0.f, 0.f, 0.f);

#pragma unroll 16
    for (int k = 0; k < 64; k++) {
        float4 w = *(float4*)&Ws[k][tx * 4];
#pragma unroll
        for (int r = 0; r < 4; r++) {
            float xv = xs[ty * 4 + r][k];
            acc[r].x = fmaf(xv, w.x, acc[r].x);
            acc[r].y = fmaf(xv, w.y, acc[r].y);
            acc[r].z = fmaf(xv, w.z, acc[r].z);
            acc[r].w = fmaf(xv, w.w, acc[r].w);
        }
    }

    int c0 = tx * 4;
    float4 bias;
    float* dst;
    if (c0 < 64) { bias = *(const float4*)&bl[c0];       dst = g_xl; }
    else         { bias = *(const float4*)&br[c0 - 64];  dst = g_xr; c0 -= 64; }
#pragma unroll
    for (int r = 0; r < 4; r++) {
        float4 v = acc[r];
        v.x += bias.x; v.y += bias.y; v.z += bias.z; v.w += bias.w;
        *(float4*)&dst[(row0 + ty * 4 + r) * 64 + c0] = v;
    }
}

// ---------------- 6) FUSED: per-dst attention + softmax + ELU + LN ---------
// One warp per destination node; 2 halves x unroll 2 = 4 edges in flight.
__device__ __forceinline__ float nan2num(float o) {
    if (!isfinite(o)) o = isnan(o) ? 0.f : (o > 0.f ? 1e6f : -1e6f);
    return o;
}

__device__ __forceinline__ float lrelu(float v) {
    return v > 0.f ? v : 0.2f * v;
}

__global__ __launch_bounds__(256)
void k_aggr_ln(const float* __restrict__ att,
               const float* __restrict__ bias_out,
               const float* __restrict__ gamma, const float* __restrict__ beta,
               float* __restrict__ dout, int to_dout) {
    int w = (blockIdx.x * blockDim.x + threadIdx.x) >> 5;   // node id
    if (w >= NN) return;
    int lane = threadIdx.x & 31;
    int half = lane >> 4;
    int l    = lane & 15;

    int beg = g_off[w], end = g_off[w + 1];

    float4 xr   = *(const float4*)&g_xr[w * 64 + l * 4];
    float4 at4  = *(const float4*)&att[l * 4];   // flat [h*32+dim]

    float4 acc = make_float4(0.f, 0.f, 0.f, 0.f);
    float  dsum = 0.f;

    // per-half steps; all 32 lanes run identical trip counts (shfl safety)
    int iters = (end - beg + 1) >> 1;            // deg >= 1 (self loop)
    for (int k = 0; k < iters; k += 2) {
        int i0 = beg + 2 * k + half;
        int i1 = i0 + 2;
        bool v0 = (i0 < end);
        bool v1 = (i1 < end);
        int  s0 = v0 ? g_srcs[i0] : g_srcs[beg];
        int  s1 = v1 ? g_srcs[i1] : g_srcs[beg];
        // both gathers issued before any dependent math -> MLP 4/warp
        float4 a0 = *(const float4*)&g_xl[s0 * 64 + l * 4];
        float4 a1 = *(const float4*)&g_xl[s1 * 64 + l * 4];

        float p0 = lrelu(a0.x + xr.x) * at4.x + lrelu(a0.y + xr.y) * at4.y
                 + lrelu(a0.z + xr.z) * at4.z + lrelu(a0.w + xr.w) * at4.w;
        float p1 = lrelu(a1.x + xr.x) * at4.x + lrelu(a1.y + xr.y) * at4.y
                 + lrelu(a1.z + xr.z) * at4.z + lrelu(a1.w + xr.w) * at4.w;
        p0 += __shfl_xor_sync(0xffffffffu, p0, 1, 8);
        p1 += __shfl_xor_sync(0xffffffffu, p1, 1, 8);
        p0 += __shfl_xor_sync(0xffffffffu, p0, 2, 8);
        p1 += __shfl_xor_sync(0xffffffffu, p1, 2, 8);
        p0 += __shfl_xor_sync(0xffffffffu, p0, 4, 8);
        p1 += __shfl_xor_sync(0xffffffffu, p1, 4, 8);
        float ex0 = v0 ? __expf(p0) : 0.f;       // scores O(1): no max shift
        float ex1 = v1 ? __expf(p1) : 0.f;
        acc.x = fmaf(ex0, a0.x, fmaf(ex1, a1.x, acc.x));
        acc.y = fmaf(ex0, a0.y, fmaf(ex1, a1.y, acc.y));
        acc.z = fmaf(ex0, a0.z, fmaf(ex1, a1.z, acc.z));
        acc.w = fmaf(ex0, a0.w, fmaf(ex1, a1.w, acc.w));
        dsum += ex0 + ex1;
    }

    // combine halves (xor 16 is symmetric: both halves end with full sums)
    acc.x += __shfl_xor_sync(0xffffffffu, acc.x, 16);
    acc.y += __shfl_xor_sync(0xffffffffu, acc.y, 16);
    acc.z += __shfl_xor_sync(0xffffffffu, acc.z, 16);
    acc.w += __shfl_xor_sync(0xffffffffu, acc.w, 16);
    dsum  += __shfl_xor_sync(0xffffffffu, dsum, 16);

    // normalize + bias_out + ELU + residual
    float inv = 1.f / (dsum + 1e-16f);           // lane's own head denom
    float4 bo = *(const float4*)&bias_out[l * 4];
    float4 rx = *(const float4*)&g_x[w * 64 + l * 4];
    float y0 = acc.x * inv + bo.x;
    float y1 = acc.y * inv + bo.y;
    float y2 = acc.z * inv + bo.z;
    float y3 = acc.w * inv + bo.w;
    y0 = y0 > 0.f ? y0 : expm1f(y0);
    y1 = y1 > 0.f ? y1 : expm1f(y1);
    y2 = y2 > 0.f ? y2 : expm1f(y2);
    y3 = y3 > 0.f ? y3 : expm1f(y3);
    y0 += rx.x; y1 += rx.y; y2 += rx.z; y3 += rx.w;

    // LayerNorm over 64 dims (butterfly over the 16-lane group)
    float sum = y0 + y1 + y2 + y3;
#pragma unroll
    for (int o = 1; o < 16; o <<= 1)
        sum += __shfl_xor_sync(0xffffffffu, sum, o, 16);
    float mu = sum * (1.f / 64.f);
    float d0 = y0 - mu, d1 = y1 - mu, d2 = y2 - mu, d3 = y3 - mu;
    float vs = d0 * d0 + d1 * d1 + d2 * d2 + d3 * d3;
#pragma unroll
    for (int o = 1; o < 16; o <<= 1)
        vs += __shfl_xor_sync(0xffffffffu, vs, o, 16);
    float r = rsqrtf(vs * (1.f / 64.f) + 1e-5f);

    float4 gm = *(const float4*)&gamma[l * 4];
    float4 bt = *(const float4*)&beta[l * 4];
    float4 o4;
    o4.x = nan2num(fmaf(d0 * r, gm.x, bt.x));
    o4.y = nan2num(fmaf(d1 * r, gm.y, bt.y));
    o4.z = nan2num(fmaf(d2 * r, gm.z, bt.z));
    o4.w = nan2num(fmaf(d3 * r, gm.w, bt.w));

    if (half == 0) {
        float* outp = to_dout ? dout : g_x;
        *(float4*)&outp[w * 64 + l * 4] = o4;
    }
}

// ---------------- host driver ----------------------------------------------
extern "C" void kernel_launch(void* const* d_in, const int* in_sizes, int n_in,
                              void* d_out, int out_size) {
    const float* coords   = (const float*)d_in[0];
    const int*   ei       = (const int*)  d_in[1];   // int32 (JAX x64 disabled)
    const float* Wp       = (const float*)d_in[2];
    const float* bp       = (const float*)d_in[3];
    const float* Wl       = (const float*)d_in[4];
    const float* bl       = (const float*)d_in[5];
    const float* Wr       = (const float*)d_in[6];
    const float* br       = (const float*)d_in[7];
    const float* att      = (const float*)d_in[8];
    const float* bias_out = (const float*)d_in[9];
    const float* gamma    = (const float*)d_in[10];
    const float* beta     = (const float*)d_in[11];
    float*       outp     = (float*)d_out;

    const int TB = 256;
    const int grid_nh = (NN * HID + TB - 1) / TB;    // 25000
    const int grid_gm = NN / 32;                     // 3125
    const int grid_ep = (EP + TB - 1) / TB;          // 6641
    const int grid_ag = (NN * 32 + TB - 1) / TB;     // 12500 (warp/node)

    // projection (+ deg zeroing) and CSR build — once, reused by all layers
    k_proj<<<grid_nh, TB>>>(coords, Wp, bp);
    k_hist<<<grid_ep, TB>>>(ei);
    k_scan1<<<NB1, SCAN_T>>>();
    k_scan2<<<1, 256>>>();
    k_scan3<<<NB1, SCAN_T>>>();
    k_scatter<<<grid_ep, TB>>>(ei);

    for (int i = 0; i < LAYERS; i++) {
        k_gemm<<<grid_gm, TB>>>(Wl + i * HID * HID, bl + i * HID,
                                Wr + i * HID * HID, br + i * HID);
        k_aggr_ln<<<grid_ag, TB>>>(att + i * HID, bias_out + i * HID,
                                   gamma + i * HID, beta + i * HID,
                                   outp, (i == LAYERS - 1) ? 1 : 0);
    }
}